// round 14
// baseline (speedup 1.0000x reference)
#include <cuda_runtime.h>
#include <cuda_fp16.h>
#include <math.h>
#include <stdint.h>

#define B_  128
#define T_  96
#define V_  4096
#define TV_ (T_*V_)
#define HB_ (B_*512)

typedef __half f16;

// ---------------- device scratch ----------------
__device__ __align__(16) float   g_enc[B_*512];
__device__ __align__(16) float   g_att1[B_*512];
__device__ __align__(16) __half2 g_att1TP[256*128];   // [k2][j]
__device__ __align__(16) __half2 g_encH2[128*256];    // [j][p]
__device__ __align__(16) float   g_h[B_*512];
__device__ __align__(16) float   g_c[B_*512];
__device__ __align__(16) float   g_att2gate[B_*1024];
__device__ __align__(16) float   g_bc1[1024];
__device__ __align__(16) float   g_bbig[2048];
__device__ __align__(16) f16     g_h2s[(T_+1)*HB_];   // ALL h states, fp16
__device__ __align__(16) f16     g_xcat2[B_*1536];    // [emb | gated awe | h]
__device__ __align__(16) f16     g_Wc1h[1024*512];
__device__ __align__(16) f16     g_Wbigh[2048*1536];  // PERMUTED rows r=4d+q
__device__ __align__(16) f16     g_Wfch[4096*512];
__device__ int g_order[B_];
__device__ int g_nvalid[T_];
__device__ unsigned g_barcnt = 0;
__device__ volatile unsigned g_bargen = 0;

// ---------------- helpers ----------------
__device__ __forceinline__ uint32_t sptr(const void* p) {
    return (uint32_t)__cvta_generic_to_shared(p);
}
__device__ __forceinline__ float sigm(float x){ return 1.f/(1.f+expf(-x)); }

#define CP16(d, s) asm volatile("cp.async.ca.shared.global [%0], [%1], 16;" :: "r"(d), "l"(s))
#define CPCOMMIT() asm volatile("cp.async.commit_group;")
#define CPWAIT1()  asm volatile("cp.async.wait_group 1;" ::: "memory")
#define CPWAIT0()  asm volatile("cp.async.wait_group 0;" ::: "memory")

// sense-reversing grid barrier across 64 CTAs (all resident on quiet machine)
__device__ __forceinline__ void gridbar64() {
    __threadfence();
    __syncthreads();
    if (threadIdx.x == 0) {
        unsigned gen = g_bargen;
        if (atomicAdd(&g_barcnt, 1) == 63) {
            g_barcnt = 0;
            __threadfence();
            g_bargen = gen + 1;
        } else {
            while (g_bargen == gen) { }
        }
        __threadfence();
    }
    __syncthreads();
}

// ---------------- prep 1: sort ----------------
__global__ void k_prep(const int* __restrict__ capl) {
    __shared__ int lens[B_];
    int i = threadIdx.x;
    lens[i] = capl[i];
    __syncthreads();
    int li = lens[i];
    int rank = 0;
    #pragma unroll 8
    for (int j = 0; j < B_; j++) {
        int lj = lens[j];
        rank += (lj > li) || (lj == li && j < i);
    }
    g_order[rank] = i;
    if (i < T_) {
        int c = 0;
        #pragma unroll 8
        for (int j = 0; j < B_; j++) c += (lens[j] > i);
        g_nvalid[i] = c;
    }
}

// ---------------- prep 2: gather ----------------
__global__ void k_gather(const float* __restrict__ enc) {
    int b = blockIdx.x;
    int o = g_order[b];
    ((float4*)g_enc)[b*128 + threadIdx.x] = ((const float4*)enc)[o*128 + threadIdx.x];
}

// ---------------- prep 3: build ALL fp16 weights ----------------
__global__ void k_buildW(const float* __restrict__ Wd, const float* __restrict__ bd,
                         const float* __restrict__ Wf, const float* __restrict__ bf,
                         const float* __restrict__ Wih, const float* __restrict__ bih,
                         const float* __restrict__ Whh, const float* __restrict__ bhh,
                         const float* __restrict__ Wfc) {
    int n = blockIdx.x, tid = threadIdx.x;
    if (n < 1024) {
        const float* src = (n < 512) ? (Wd + (size_t)n*512) : (Wf + (size_t)(n-512)*512);
        f16* d = g_Wc1h + (size_t)n*512;
        for (int k = tid; k < 512; k += 128) d[k] = __float2half(src[k]);
        if (tid == 0) g_bc1[n] = (n < 512) ? bd[n] : bf[n-512];
    } else if (n < 3072) {
        int r = n - 1024;
        int dd = r >> 2, q = r & 3;
        int s = q*512 + dd;
        f16* d = g_Wbigh + (size_t)r*1536;
        for (int k = tid; k < 1536; k += 128) {
            float w = (k < 1024) ? Wih[(size_t)s*1024 + k] : Whh[(size_t)s*512 + k - 1024];
            d[k] = __float2half(w);
        }
        if (tid == 0) g_bbig[r] = bih[s] + bhh[s];
    } else {
        int r = n - 3072;
        f16* d = g_Wfch + (size_t)r*512;
        const float* src = Wfc + (size_t)r*512;
        for (int k = tid; k < 512; k += 128) d[k] = __float2half(src[k]);
    }
}

// ---------------- prep 4: triple fp32 GEMM (h0, c0, att1) ----------------
__global__ void __launch_bounds__(256) k_gemm32t(
    const float* __restrict__ W0, const float* __restrict__ b0,
    const float* __restrict__ W1, const float* __restrict__ b1,
    const float* __restrict__ W2, const float* __restrict__ b2)
{
    const float* W    = (blockIdx.z == 0) ? W0 : (blockIdx.z == 1) ? W1 : W2;
    const float* bias = (blockIdx.z == 0) ? b0 : (blockIdx.z == 1) ? b1 : b2;
    float* out        = (blockIdx.z == 0) ? g_h : (blockIdx.z == 1) ? g_c : g_att1;
    const int K = 512;

    __shared__ float As[16][36];
    __shared__ float Bs[16][36];
    const int row0 = blockIdx.y * 32, col0 = blockIdx.x * 32;
    const int tid = threadIdx.x;
    const int tm = tid >> 4, tn = tid & 15;
    const int ar = tid >> 3, ak = (tid & 7) * 2;
    const float* Ap = g_enc + (size_t)(row0 + ar)*K + ak;
    const float* Wp = W + (size_t)(col0 + ar)*K + ak;
    float acc[2][2] = {{0,0},{0,0}};
    for (int k0 = 0; k0 < K; k0 += 16) {
        float2 va = *(const float2*)(Ap + k0);
        float2 vw = *(const float2*)(Wp + k0);
        __syncthreads();
        As[ak][ar] = va.x; As[ak+1][ar] = va.y;
        Bs[ak][ar] = vw.x; Bs[ak+1][ar] = vw.y;
        __syncthreads();
        #pragma unroll
        for (int kk = 0; kk < 16; kk++) {
            float a0 = As[kk][tm*2], a1 = As[kk][tm*2+1];
            float b0v = Bs[kk][tn*2], b1v = Bs[kk][tn*2+1];
            acc[0][0] = fmaf(a0, b0v, acc[0][0]);
            acc[0][1] = fmaf(a0, b1v, acc[0][1]);
            acc[1][0] = fmaf(a1, b0v, acc[1][0]);
            acc[1][1] = fmaf(a1, b1v, acc[1][1]);
        }
    }
    #pragma unroll
    for (int i = 0; i < 2; i++)
        #pragma unroll
        for (int j = 0; j < 2; j++) {
            int r = row0 + tm*2 + i, cdx = col0 + tn*2 + j;
            out[(size_t)r*512 + cdx] = acc[i][j] + bias[cdx];
        }
}

// ---------------- prep 5: pack att1T/enc + h0 ----------------
__global__ void k_post() {
    int b = blockIdx.x, tid = threadIdx.x;
    if (tid < 256) {
        float x0 = g_att1[b*512 + 2*tid], x1 = g_att1[b*512 + 2*tid + 1];
        g_att1TP[tid*128 + b] = __floats2half2_rn(x0, x1);
        g_encH2[b*256 + tid] = __floats2half2_rn(g_enc[b*512 + 2*tid], g_enc[b*512 + 2*tid + 1]);
    }
    #pragma unroll
    for (int u = 0; u < 2; u++) {
        int d = tid + 256*u;
        g_h2s[b*512 + d] = __float2half(g_h[b*512 + d]);
    }
}

// ---------------- fp16 MMA tile body: K-slab 128, 3-stage ring ----------------
// BM=32, BN=64, 256 threads. Stage = A(32x136, 8704B) + B(64x136, 17408B) = 26112B.
// EPI 1: att2gate (sigmoid cols>=512)   EPI 2: gates + fused LSTM
// EPI 3: preds -> out[r,t,:] with zero-fill of invalid rows
#define STAGE_B 26112
template<int EPI>
__device__ __forceinline__ void mma_body(
    const f16* __restrict__ A2, const f16* __restrict__ W2,
    const float* __restrict__ bias, float* __restrict__ out,
    f16* __restrict__ h2out, int Keff, int nv, int t, int ldc,
    int row0, int col0, char* dsm)
{
    const uint32_t sb0 = sptr(dsm);
    const int tid = threadIdx.x;

    if (row0 >= nv) {
        if (EPI == 3) {
            float4 z = make_float4(0.f, 0.f, 0.f, 0.f);
            for (int x = tid; x < 512; x += 256) {
                int r = x >> 4, c4 = (x & 15) * 4;
                *(float4*)(out + (size_t)(row0 + r)*TV_ + (size_t)t*V_ + col0 + c4) = z;
            }
        }
        return;
    }

    const int warp = tid >> 5, lane = tid & 31;
    const int mw = warp & 1, nw = warp >> 1;

    const int seg = tid & 15;
    uint32_t adst[2], bdst[4];
    const f16* asrc[2];
    const f16* bsrc[4];
    #pragma unroll
    for (int i = 0; i < 2; i++) {
        int row = (tid + 256*i) >> 4;
        adst[i] = row*272 + seg*16;
        asrc[i] = A2 + (size_t)(row0 + row)*Keff + seg*8;
    }
    #pragma unroll
    for (int i = 0; i < 4; i++) {
        int row = (tid + 256*i) >> 4;
        bdst[i] = 8704 + row*272 + seg*16;
        bsrc[i] = W2 + (size_t)(col0 + row)*Keff + seg*8;
    }

    auto ld = [&](int st, int s) {
        uint32_t base = sb0 + st*STAGE_B;
        #pragma unroll
        for (int i = 0; i < 2; i++) CP16(base + adst[i], asrc[i] + s*128);
        #pragma unroll
        for (int i = 0; i < 4; i++) CP16(base + bdst[i], bsrc[i] + s*128);
        CPCOMMIT();
    };

    const int a_m = mw*16 + (lane & 7) + ((lane >> 3) & 1)*8;
    const int a_k = ((lane >> 4) & 1)*8;
    const int aoff = a_m*136 + a_k;
    const int b_n = nw*16 + (lane & 7) + ((lane >> 4) & 1)*8;
    const int b_k = ((lane >> 3) & 1)*8;
    const int boff = b_n*136 + b_k;

    float acc[2][4];
    #pragma unroll
    for (int b = 0; b < 2; b++)
        #pragma unroll
        for (int j = 0; j < 4; j++) acc[b][j] = 0.f;

    const int S = Keff >> 7;   // 4 or 12
    ld(0, 0);
    ld(1, 1);

    for (int s = 0; s < S; s++) {
        CPWAIT1();
        __syncthreads();
        const int buf = s % 3;
        const uint32_t abase = sb0 + buf*STAGE_B;
        const uint32_t bbase = abase + 8704;
        #pragma unroll
        for (int k16 = 0; k16 < 8; k16++) {
            uint32_t a0, a1, a2, a3;
            uint32_t ad = abase + (aoff + k16*16)*2;
            asm volatile("ldmatrix.sync.aligned.m8n8.x4.shared.b16 {%0,%1,%2,%3}, [%4];"
                         : "=r"(a0), "=r"(a1), "=r"(a2), "=r"(a3) : "r"(ad));
            uint32_t b0, b1, b2, b3;
            uint32_t bd = bbase + (boff + k16*16)*2;
            asm volatile("ldmatrix.sync.aligned.m8n8.x4.shared.b16 {%0,%1,%2,%3}, [%4];"
                         : "=r"(b0), "=r"(b1), "=r"(b2), "=r"(b3) : "r"(bd));
            asm volatile("mma.sync.aligned.m16n8k16.row.col.f32.f16.f16.f32 "
                         "{%0,%1,%2,%3},{%4,%5,%6,%7},{%8,%9},{%0,%1,%2,%3};"
                         : "+f"(acc[0][0]), "+f"(acc[0][1]), "+f"(acc[0][2]), "+f"(acc[0][3])
                         : "r"(a0), "r"(a1), "r"(a2), "r"(a3), "r"(b0), "r"(b1));
            asm volatile("mma.sync.aligned.m16n8k16.row.col.f32.f16.f16.f32 "
                         "{%0,%1,%2,%3},{%4,%5,%6,%7},{%8,%9},{%0,%1,%2,%3};"
                         : "+f"(acc[1][0]), "+f"(acc[1][1]), "+f"(acc[1][2]), "+f"(acc[1][3])
                         : "r"(a0), "r"(a1), "r"(a2), "r"(a3), "r"(b2), "r"(b3));
        }
        int nxt = s + 2;
        if (nxt < S) ld(nxt % 3, nxt); else CPCOMMIT();
    }

    const int g = lane >> 2, tg = lane & 3;
    const int rbase = row0 + mw*16;

    if (EPI == 2) {
        #pragma unroll
        for (int b = 0; b < 2; b++) {
            int ncol = col0 + nw*16 + b*8 + tg*2;
            float v00 = acc[b][0] + bias[ncol];
            float v01 = acc[b][1] + bias[ncol+1];
            float v10 = acc[b][2] + bias[ncol];
            float v11 = acc[b][3] + bias[ncol+1];
            float p00 = __shfl_xor_sync(0xffffffffu, v00, 1);
            float p01 = __shfl_xor_sync(0xffffffffu, v01, 1);
            float p10 = __shfl_xor_sync(0xffffffffu, v10, 1);
            float p11 = __shfl_xor_sync(0xffffffffu, v11, 1);
            if (!(lane & 1)) {
                int d = ncol >> 2;
                int r0 = rbase + g, r1 = r0 + 8;
                {
                    float gi = sigm(v00), gf = sigm(v01);
                    float gg = tanhf(p00), go = sigm(p01);
                    float c = gf * g_c[r0*512 + d] + gi * gg;
                    float h = go * tanhf(c);
                    g_c[r0*512 + d] = c;
                    h2out[r0*512 + d] = __float2half(h);
                }
                {
                    float gi = sigm(v10), gf = sigm(v11);
                    float gg = tanhf(p10), go = sigm(p11);
                    float c = gf * g_c[r1*512 + d] + gi * gg;
                    float h = go * tanhf(c);
                    g_c[r1*512 + d] = c;
                    h2out[r1*512 + d] = __float2half(h);
                }
            }
        }
        return;
    }

    #pragma unroll
    for (int b = 0; b < 2; b++) {
        int ncol = col0 + nw*16 + b*8 + tg*2;
        float v00 = acc[b][0] + bias[ncol];
        float v01 = acc[b][1] + bias[ncol+1];
        float v10 = acc[b][2] + bias[ncol];
        float v11 = acc[b][3] + bias[ncol+1];
        if (EPI == 1 && ncol >= 512) {
            v00 = sigm(v00); v01 = sigm(v01);
            v10 = sigm(v10); v11 = sigm(v11);
        }
        int r0 = rbase + g, r1 = r0 + 8;
        if (EPI == 3) {
            float2 z = make_float2(0.f, 0.f);
            float2 w0 = (r0 < nv) ? make_float2(v00, v01) : z;
            float2 w1 = (r1 < nv) ? make_float2(v10, v11) : z;
            *(float2*)(out + (size_t)r0*TV_ + (size_t)t*V_ + ncol) = w0;
            *(float2*)(out + (size_t)r1*TV_ + (size_t)t*V_ + ncol) = w1;
        } else {
            *(float2*)(out + (size_t)r0*ldc + ncol) = make_float2(v00, v01);
            *(float2*)(out + (size_t)r1*ldc + ncol) = make_float2(v10, v11);
        }
    }
}

// ---------------- attention job: 2 rows, 256 threads ----------------
__device__ void attn_job(const int* __restrict__ caps, const float* __restrict__ emb,
                         const float* __restrict__ wfull, const float* __restrict__ bfull,
                         int t, const f16* __restrict__ h2in,
                         int i0, int nv, char* smemraw)
{
    if (i0 >= nv) return;
    const bool two = (i0 + 1 < nv);

    float* s_a2 = (float*)smemraw;        // [2][512]
    float* s_wf = s_a2 + 1024;            // [512]
    float* s_p  = s_wf + 512;             // [4][128]
    float* s_sc = s_p + 512;              // [2][128]
    float* s_al = s_sc + 256;             // [2][128]

    const int tid = threadIdx.x;
    #pragma unroll
    for (int u = 0; u < 2; u++) {
        int k = tid + 256*u;
        s_a2[k]       = g_att2gate[i0*1024 + k];
        s_a2[512 + k] = two ? g_att2gate[(i0+1)*1024 + k] : 0.f;
        s_wf[k]       = wfull[k];
    }
    __syncthreads();

    // scores: j = tid&127, ks = tid>>7 covers k2 in [ks*128, ks*128+128)
    const int j = tid & 127, ks = tid >> 7;
    float p0 = 0.f, p1 = 0.f;
    const __half2* ap = g_att1TP + (size_t)(ks*128)*128 + j;
    #pragma unroll 8
    for (int k2 = 0; k2 < 128; k2++) {
        float2 v = __half22float2(ap[(size_t)k2*128]);
        int k = ks*256 + 2*k2;
        p0 = fmaf(fmaxf(v.x + s_a2[k],   0.f), s_wf[k],   p0);
        p0 = fmaf(fmaxf(v.y + s_a2[k+1], 0.f), s_wf[k+1], p0);
        p1 = fmaf(fmaxf(v.x + s_a2[512 + k],   0.f), s_wf[k],   p1);
        p1 = fmaf(fmaxf(v.y + s_a2[512 + k+1], 0.f), s_wf[k+1], p1);
    }
    s_p[(ks*2 + 0)*128 + j] = p0;
    s_p[(ks*2 + 1)*128 + j] = p1;
    __syncthreads();

    {
        int row = tid >> 7, jj = tid & 127;
        float sc = s_p[row*128 + jj] + s_p[(2 + row)*128 + jj] + bfull[0];
        s_sc[row*128 + jj] = (jj < nv) ? sc : -3.0e38f;
    }
    __syncthreads();

    if (tid < 64) {
        int row = tid >> 5, l = tid & 31;
        float vv[4], m = -3.0e38f;
        #pragma unroll
        for (int u = 0; u < 4; u++) { vv[u] = s_sc[row*128 + l + 32*u]; m = fmaxf(m, vv[u]); }
        #pragma unroll
        for (int o = 16; o > 0; o >>= 1) m = fmaxf(m, __shfl_xor_sync(0xffffffffu, m, o));
        float sum = 0.f;
        #pragma unroll
        for (int u = 0; u < 4; u++) { vv[u] = expf(vv[u] - m); sum += vv[u]; }
        #pragma unroll
        for (int o = 16; o > 0; o >>= 1) sum += __shfl_xor_sync(0xffffffffu, sum, o);
        float inv = 1.f / sum;
        #pragma unroll
        for (int u = 0; u < 4; u++) s_al[row*128 + l + 32*u] = vv[u] * inv;
    }
    __syncthreads();

    // awe: thread p = tid computes half2 dim p for BOTH rows
    const int p = tid;
    const __half2* ep = g_encH2 + p;
    float ax0 = 0.f, ay0 = 0.f, ax1 = 0.f, ay1 = 0.f;
    #pragma unroll 4
    for (int jj = 0; jj < 128; jj++) {
        float2 e = __half22float2(ep[(size_t)jj*256]);
        float a0 = s_al[jj];
        float a1 = s_al[128 + jj];
        ax0 = fmaf(a0, e.x, ax0);
        ay0 = fmaf(a0, e.y, ay0);
        ax1 = fmaf(a1, e.x, ax1);
        ay1 = fmaf(a1, e.y, ay1);
    }

    const int d0 = 2*p;
    #pragma unroll
    for (int r = 0; r < 2; r++) {
        if (r == 1 && !two) break;
        const int i = i0 + r;
        float ax = (r == 0) ? ax0 : ax1;
        float ay = (r == 0) ? ay0 : ay1;
        int cap = caps[g_order[i]*T_ + t];
        f16* xr = g_xcat2 + (size_t)i*1536;
        xr[d0]   = __float2half(emb[(size_t)cap*512 + d0]);
        xr[d0+1] = __float2half(emb[(size_t)cap*512 + d0 + 1]);
        float gt0 = g_att2gate[i*1024 + 512 + d0];
        float gt1 = g_att2gate[i*1024 + 512 + d0 + 1];
        xr[512 + d0]   = __float2half(gt0 * ax);
        xr[512 + d0+1] = __float2half(gt1 * ay);
        xr[1024 + d0]   = h2in[i*512 + d0];
        xr[1024 + d0+1] = h2in[i*512 + d0 + 1];
    }
}

// ---------------- fused a2g + attention (64 CTAs, quiet machine) ----------------
__global__ void __launch_bounds__(256) k_fused(
    const int* __restrict__ caps, const float* __restrict__ emb,
    const float* __restrict__ wfull, const float* __restrict__ bfull,
    int t, const f16* __restrict__ hin)
{
    extern __shared__ __align__(16) char dsm[];
    const int nv = g_nvalid[t];

    // phase 1: one a2g MMA tile per CTA (4 row-blocks x 16 col-tiles)
    mma_body<1>(hin, g_Wc1h, g_bc1, g_att2gate, nullptr, 512, nv, t, 1024,
                (blockIdx.x >> 4)*32, (blockIdx.x & 15)*64, dsm);
    CPWAIT0();
    gridbar64();

    // phase 2: attention for 2 batch rows per CTA (smem reused)
    attn_job(caps, emb, wfull, bfull, t, hin, blockIdx.x*2, nv, dsm);
}

// gates kernel
__global__ void __launch_bounds__(256) k_gates(int t) {
    extern __shared__ __align__(16) char dsm[];
    const int nv = g_nvalid[t];
    f16* hout = g_h2s + (size_t)(t + 1) * HB_;
    mma_body<2>(g_xcat2, g_Wbigh, g_bbig, nullptr, hout, 1536, nv, t, 0,
                blockIdx.y*32, blockIdx.x*64, dsm);
}

// mega preds kernel: all 96 steps in one launch
__global__ void __launch_bounds__(256) k_preds(
    const float* __restrict__ bfc, float* __restrict__ out)
{
    extern __shared__ __align__(16) char dsm[];
    const int t = blockIdx.z;
    const int nv = g_nvalid[t];
    const f16* hin = g_h2s + (size_t)(t + 1) * HB_;
    mma_body<3>(hin, g_Wfch, bfc, out, nullptr, 512, nv, t, 0,
                blockIdx.y*32, blockIdx.x*64, dsm);
}

// ---------------- host launch ----------------
extern "C" void kernel_launch(void* const* d_in, const int* in_sizes, int n_in,
                              void* d_out, int out_size) {
    const float* encoder_out = (const float*)d_in[0];
    const int*   caps        = (const int*)  d_in[1];
    const int*   capl        = (const int*)  d_in[2];
    const float* W_enc  = (const float*)d_in[3];
    const float* b_enc  = (const float*)d_in[4];
    const float* W_dec  = (const float*)d_in[5];
    const float* b_dec  = (const float*)d_in[6];
    const float* W_full = (const float*)d_in[7];
    const float* b_full = (const float*)d_in[8];
    const float* W_init_h = (const float*)d_in[9];
    const float* b_init_h = (const float*)d_in[10];
    const float* W_init_c = (const float*)d_in[11];
    const float* b_init_c = (const float*)d_in[12];
    const float* W_fbeta  = (const float*)d_in[13];
    const float* b_fbeta  = (const float*)d_in[14];
    const float* W_fc     = (const float*)d_in[15];
    const float* b_fc     = (const float*)d_in[16];
    const float* emb      = (const float*)d_in[17];
    const float* W_ih     = (const float*)d_in[18];
    const float* b_ih     = (const float*)d_in[19];
    const float* W_hh     = (const float*)d_in[20];
    const float* b_hh     = (const float*)d_in[21];
    float* out = (float*)d_out;

    f16 *p_h2s;
    cudaGetSymbolAddress((void**)&p_h2s, g_h2s);

    static bool init = false;
    if (!init) {
        init = true;
        const int SM = 3*STAGE_B;
        cudaFuncSetAttribute(k_fused, cudaFuncAttributeMaxDynamicSharedMemorySize, SM);
        cudaFuncSetAttribute(k_gates, cudaFuncAttributeMaxDynamicSharedMemorySize, SM);
        cudaFuncSetAttribute(k_preds, cudaFuncAttributeMaxDynamicSharedMemorySize, SM);
    }
    const int SMEM_MMA = 3*STAGE_B;

    // ---- prep ----
    k_prep<<<1, 128>>>(capl);
    k_gather<<<128, 128>>>(encoder_out);
    k_buildW<<<7168, 128>>>(W_dec, b_dec, W_fbeta, b_fbeta,
                            W_ih, b_ih, W_hh, b_hh, W_fc);
    k_gemm32t<<<dim3(16,4,3), 256>>>(W_init_h, b_init_h, W_init_c, b_init_c, W_enc, b_enc);
    k_post<<<128, 256>>>();

    // ---- recurrence on a quiet machine: 2 launches/step ----
    for (int t = 0; t < T_; t++) {
        const f16* hin = p_h2s + (size_t)t * HB_;
        k_fused<<<64, 256, SMEM_MMA>>>(caps, emb, W_full, b_full, t, hin);
        k_gates<<<dim3(32,4), 256, SMEM_MMA>>>(t);
    }

    // ---- all preds in one dense mega-GEMM at the end ----
    k_preds<<<dim3(64, 4, T_), 256, SMEM_MMA>>>(b_fc, out);
}

// round 15
// speedup vs baseline: 1.1890x; 1.1890x over previous
#include <cuda_runtime.h>
#include <cuda_fp16.h>
#include <math.h>
#include <stdint.h>

#define B_  128
#define T_  96
#define V_  4096
#define TV_ (T_*V_)
#define HB_ (B_*512)

typedef __half f16;

// ---------------- device scratch ----------------
__device__ __align__(16) float   g_enc[B_*512];
__device__ __align__(16) float   g_att1[B_*512];
__device__ __align__(16) __half2 g_att1TP[256*128];   // [k2][j]
__device__ __align__(16) __half2 g_encH2[128*256];    // [j][p]
__device__ __align__(16) float   g_h[B_*512];
__device__ __align__(16) float   g_c[B_*512];
__device__ __align__(16) float   g_att2gate[B_*1024];
__device__ __align__(16) float   g_bc1[1024];
__device__ __align__(16) float   g_bbig[2048];
__device__ __align__(16) f16     g_h2s[(T_+1)*HB_];   // ALL h states, fp16
__device__ __align__(16) f16     g_xcat2[B_*1536];    // [emb | gated awe | h]
__device__ __align__(16) f16     g_Wc1h[1024*512];
__device__ __align__(16) f16     g_Wbigh[2048*1536];  // PERMUTED rows r=4d+q
__device__ __align__(16) f16     g_Wfch[4096*512];
__device__ int g_order[B_];
__device__ int g_nvalid[T_];

// ---------------- helpers ----------------
__device__ __forceinline__ uint32_t sptr(const void* p) {
    return (uint32_t)__cvta_generic_to_shared(p);
}
__device__ __forceinline__ float sigm(float x){ return 1.f/(1.f+expf(-x)); }

#define CP16(d, s) asm volatile("cp.async.ca.shared.global [%0], [%1], 16;" :: "r"(d), "l"(s))
#define CPCOMMIT() asm volatile("cp.async.commit_group;")
#define CPWAIT1()  asm volatile("cp.async.wait_group 1;" ::: "memory")

// ---------------- prep 1: sort ----------------
__global__ void k_prep(const int* __restrict__ capl) {
    __shared__ int lens[B_];
    int i = threadIdx.x;
    lens[i] = capl[i];
    __syncthreads();
    int li = lens[i];
    int rank = 0;
    #pragma unroll 8
    for (int j = 0; j < B_; j++) {
        int lj = lens[j];
        rank += (lj > li) || (lj == li && j < i);
    }
    g_order[rank] = i;
    if (i < T_) {
        int c = 0;
        #pragma unroll 8
        for (int j = 0; j < B_; j++) c += (lens[j] > i);
        g_nvalid[i] = c;
    }
}

// ---------------- prep 2: gather ----------------
__global__ void k_gather(const float* __restrict__ enc) {
    int b = blockIdx.x;
    int o = g_order[b];
    ((float4*)g_enc)[b*128 + threadIdx.x] = ((const float4*)enc)[o*128 + threadIdx.x];
}

// ---------------- prep 3: build ALL fp16 weights ----------------
__global__ void k_buildW(const float* __restrict__ Wd, const float* __restrict__ bd,
                         const float* __restrict__ Wf, const float* __restrict__ bf,
                         const float* __restrict__ Wih, const float* __restrict__ bih,
                         const float* __restrict__ Whh, const float* __restrict__ bhh,
                         const float* __restrict__ Wfc) {
    int n = blockIdx.x, tid = threadIdx.x;
    if (n < 1024) {
        const float* src = (n < 512) ? (Wd + (size_t)n*512) : (Wf + (size_t)(n-512)*512);
        f16* d = g_Wc1h + (size_t)n*512;
        for (int k = tid; k < 512; k += 128) d[k] = __float2half(src[k]);
        if (tid == 0) g_bc1[n] = (n < 512) ? bd[n] : bf[n-512];
    } else if (n < 3072) {
        int r = n - 1024;
        int dd = r >> 2, q = r & 3;
        int s = q*512 + dd;
        f16* d = g_Wbigh + (size_t)r*1536;
        for (int k = tid; k < 1536; k += 128) {
            float w = (k < 1024) ? Wih[(size_t)s*1024 + k] : Whh[(size_t)s*512 + k - 1024];
            d[k] = __float2half(w);
        }
        if (tid == 0) g_bbig[r] = bih[s] + bhh[s];
    } else {
        int r = n - 3072;
        f16* d = g_Wfch + (size_t)r*512;
        const float* src = Wfc + (size_t)r*512;
        for (int k = tid; k < 512; k += 128) d[k] = __float2half(src[k]);
    }
}

// ---------------- prep 4: triple fp32 GEMM (h0, c0, att1) ----------------
__global__ void __launch_bounds__(256) k_gemm32t(
    const float* __restrict__ W0, const float* __restrict__ b0,
    const float* __restrict__ W1, const float* __restrict__ b1,
    const float* __restrict__ W2, const float* __restrict__ b2)
{
    const float* W    = (blockIdx.z == 0) ? W0 : (blockIdx.z == 1) ? W1 : W2;
    const float* bias = (blockIdx.z == 0) ? b0 : (blockIdx.z == 1) ? b1 : b2;
    float* out        = (blockIdx.z == 0) ? g_h : (blockIdx.z == 1) ? g_c : g_att1;
    const int K = 512;

    __shared__ float As[16][36];
    __shared__ float Bs[16][36];
    const int row0 = blockIdx.y * 32, col0 = blockIdx.x * 32;
    const int tid = threadIdx.x;
    const int tm = tid >> 4, tn = tid & 15;
    const int ar = tid >> 3, ak = (tid & 7) * 2;
    const float* Ap = g_enc + (size_t)(row0 + ar)*K + ak;
    const float* Wp = W + (size_t)(col0 + ar)*K + ak;
    float acc[2][2] = {{0,0},{0,0}};
    for (int k0 = 0; k0 < K; k0 += 16) {
        float2 va = *(const float2*)(Ap + k0);
        float2 vw = *(const float2*)(Wp + k0);
        __syncthreads();
        As[ak][ar] = va.x; As[ak+1][ar] = va.y;
        Bs[ak][ar] = vw.x; Bs[ak+1][ar] = vw.y;
        __syncthreads();
        #pragma unroll
        for (int kk = 0; kk < 16; kk++) {
            float a0 = As[kk][tm*2], a1 = As[kk][tm*2+1];
            float b0v = Bs[kk][tn*2], b1v = Bs[kk][tn*2+1];
            acc[0][0] = fmaf(a0, b0v, acc[0][0]);
            acc[0][1] = fmaf(a0, b1v, acc[0][1]);
            acc[1][0] = fmaf(a1, b0v, acc[1][0]);
            acc[1][1] = fmaf(a1, b1v, acc[1][1]);
        }
    }
    #pragma unroll
    for (int i = 0; i < 2; i++)
        #pragma unroll
        for (int j = 0; j < 2; j++) {
            int r = row0 + tm*2 + i, cdx = col0 + tn*2 + j;
            out[(size_t)r*512 + cdx] = acc[i][j] + bias[cdx];
        }
}

// ---------------- prep 5: pack att1T/enc + h0 ----------------
__global__ void k_post() {
    int b = blockIdx.x, tid = threadIdx.x;
    if (tid < 256) {
        float x0 = g_att1[b*512 + 2*tid], x1 = g_att1[b*512 + 2*tid + 1];
        g_att1TP[tid*128 + b] = __floats2half2_rn(x0, x1);
        g_encH2[b*256 + tid] = __floats2half2_rn(g_enc[b*512 + 2*tid], g_enc[b*512 + 2*tid + 1]);
    }
    #pragma unroll
    for (int u = 0; u < 2; u++) {
        int d = tid + 256*u;
        g_h2s[b*512 + d] = __float2half(g_h[b*512 + d]);
    }
}

// ---------------- fp16 MMA GEMM: K-slab 128, 3-stage dynamic-smem ring ----------------
// BM=32, BN=64, 256 threads. Stage = A(32x136, 8704B) + B(64x136, 17408B) = 26112B.
// EPI 1: att2gate (sigmoid cols>=512)   EPI 2: gates + fused LSTM
// EPI 3: preds -> out[r,t,:] with zero-fill of invalid rows
#define STAGE_B 26112
template<int EPI>
__global__ void __launch_bounds__(256) k_mma(
    const f16* __restrict__ A2, const f16* __restrict__ W2,
    const float* __restrict__ bias, float* __restrict__ out,
    f16* __restrict__ h2out, int Keff, int t, int ldc)
{
    extern __shared__ __align__(16) char dsm[];
    const uint32_t sb0 = sptr(dsm);

    const int nv   = (t >= 0) ? g_nvalid[t] : B_;
    const int row0 = blockIdx.y * 32;
    const int col0 = blockIdx.x * 64;
    const int tid  = threadIdx.x;

    if (row0 >= nv) {
        if (EPI == 3) {
            float4 z = make_float4(0.f, 0.f, 0.f, 0.f);
            for (int x = tid; x < 512; x += 256) {
                int r = x >> 4, c4 = (x & 15) * 4;
                *(float4*)(out + (size_t)(row0 + r)*TV_ + (size_t)t*V_ + col0 + c4) = z;
            }
        }
        return;
    }

    const int warp = tid >> 5, lane = tid & 31;
    const int mw = warp & 1, nw = warp >> 1;

    const int seg = tid & 15;
    uint32_t adst[2], bdst[4];
    const f16* asrc[2];
    const f16* bsrc[4];
    #pragma unroll
    for (int i = 0; i < 2; i++) {
        int row = (tid + 256*i) >> 4;
        adst[i] = row*272 + seg*16;
        asrc[i] = A2 + (size_t)(row0 + row)*Keff + seg*8;
    }
    #pragma unroll
    for (int i = 0; i < 4; i++) {
        int row = (tid + 256*i) >> 4;
        bdst[i] = 8704 + row*272 + seg*16;
        bsrc[i] = W2 + (size_t)(col0 + row)*Keff + seg*8;
    }

    auto ld = [&](int st, int s) {
        uint32_t base = sb0 + st*STAGE_B;
        #pragma unroll
        for (int i = 0; i < 2; i++) CP16(base + adst[i], asrc[i] + s*128);
        #pragma unroll
        for (int i = 0; i < 4; i++) CP16(base + bdst[i], bsrc[i] + s*128);
        CPCOMMIT();
    };

    const int a_m = mw*16 + (lane & 7) + ((lane >> 3) & 1)*8;
    const int a_k = ((lane >> 4) & 1)*8;
    const int aoff = a_m*136 + a_k;
    const int b_n = nw*16 + (lane & 7) + ((lane >> 4) & 1)*8;
    const int b_k = ((lane >> 3) & 1)*8;
    const int boff = b_n*136 + b_k;

    float acc[2][4];
    #pragma unroll
    for (int b = 0; b < 2; b++)
        #pragma unroll
        for (int j = 0; j < 4; j++) acc[b][j] = 0.f;

    const int S = Keff >> 7;   // 4 or 12
    ld(0, 0);
    ld(1, 1);

    for (int s = 0; s < S; s++) {
        CPWAIT1();
        __syncthreads();
        const int buf = s % 3;
        const uint32_t abase = sb0 + buf*STAGE_B;
        const uint32_t bbase = abase + 8704;
        #pragma unroll
        for (int k16 = 0; k16 < 8; k16++) {
            uint32_t a0, a1, a2, a3;
            uint32_t ad = abase + (aoff + k16*16)*2;
            asm volatile("ldmatrix.sync.aligned.m8n8.x4.shared.b16 {%0,%1,%2,%3}, [%4];"
                         : "=r"(a0), "=r"(a1), "=r"(a2), "=r"(a3) : "r"(ad));
            uint32_t b0, b1, b2, b3;
            uint32_t bd = bbase + (boff + k16*16)*2;
            asm volatile("ldmatrix.sync.aligned.m8n8.x4.shared.b16 {%0,%1,%2,%3}, [%4];"
                         : "=r"(b0), "=r"(b1), "=r"(b2), "=r"(b3) : "r"(bd));
            asm volatile("mma.sync.aligned.m16n8k16.row.col.f32.f16.f16.f32 "
                         "{%0,%1,%2,%3},{%4,%5,%6,%7},{%8,%9},{%0,%1,%2,%3};"
                         : "+f"(acc[0][0]), "+f"(acc[0][1]), "+f"(acc[0][2]), "+f"(acc[0][3])
                         : "r"(a0), "r"(a1), "r"(a2), "r"(a3), "r"(b0), "r"(b1));
            asm volatile("mma.sync.aligned.m16n8k16.row.col.f32.f16.f16.f32 "
                         "{%0,%1,%2,%3},{%4,%5,%6,%7},{%8,%9},{%0,%1,%2,%3};"
                         : "+f"(acc[1][0]), "+f"(acc[1][1]), "+f"(acc[1][2]), "+f"(acc[1][3])
                         : "r"(a0), "r"(a1), "r"(a2), "r"(a3), "r"(b2), "r"(b3));
        }
        int nxt = s + 2;
        if (nxt < S) ld(nxt % 3, nxt); else CPCOMMIT();
    }

    const int g = lane >> 2, tg = lane & 3;
    const int rbase = row0 + mw*16;

    if (EPI == 2) {
        #pragma unroll
        for (int b = 0; b < 2; b++) {
            int ncol = col0 + nw*16 + b*8 + tg*2;
            float v00 = acc[b][0] + bias[ncol];
            float v01 = acc[b][1] + bias[ncol+1];
            float v10 = acc[b][2] + bias[ncol];
            float v11 = acc[b][3] + bias[ncol+1];
            float p00 = __shfl_xor_sync(0xffffffffu, v00, 1);
            float p01 = __shfl_xor_sync(0xffffffffu, v01, 1);
            float p10 = __shfl_xor_sync(0xffffffffu, v10, 1);
            float p11 = __shfl_xor_sync(0xffffffffu, v11, 1);
            if (!(lane & 1)) {
                int d = ncol >> 2;
                int r0 = rbase + g, r1 = r0 + 8;
                {
                    float gi = sigm(v00), gf = sigm(v01);
                    float gg = tanhf(p00), go = sigm(p01);
                    float c = gf * g_c[r0*512 + d] + gi * gg;
                    float h = go * tanhf(c);
                    g_c[r0*512 + d] = c;
                    h2out[r0*512 + d] = __float2half(h);
                }
                {
                    float gi = sigm(v10), gf = sigm(v11);
                    float gg = tanhf(p10), go = sigm(p11);
                    float c = gf * g_c[r1*512 + d] + gi * gg;
                    float h = go * tanhf(c);
                    g_c[r1*512 + d] = c;
                    h2out[r1*512 + d] = __float2half(h);
                }
            }
        }
        return;
    }

    #pragma unroll
    for (int b = 0; b < 2; b++) {
        int ncol = col0 + nw*16 + b*8 + tg*2;
        float v00 = acc[b][0] + bias[ncol];
        float v01 = acc[b][1] + bias[ncol+1];
        float v10 = acc[b][2] + bias[ncol];
        float v11 = acc[b][3] + bias[ncol+1];
        if (EPI == 1 && ncol >= 512) {
            v00 = sigm(v00); v01 = sigm(v01);
            v10 = sigm(v10); v11 = sigm(v11);
        }
        int r0 = rbase + g, r1 = r0 + 8;
        if (EPI == 3) {
            float2 z = make_float2(0.f, 0.f);
            float2 w0 = (r0 < nv) ? make_float2(v00, v01) : z;
            float2 w1 = (r1 < nv) ? make_float2(v10, v11) : z;
            *(float2*)(out + (size_t)r0*TV_ + (size_t)t*V_ + ncol) = w0;
            *(float2*)(out + (size_t)r1*TV_ + (size_t)t*V_ + ncol) = w1;
        } else {
            *(float2*)(out + (size_t)r0*ldc + ncol) = make_float2(v00, v01);
            *(float2*)(out + (size_t)r1*ldc + ncol) = make_float2(v10, v11);
        }
    }
}

// ---------------- attention: 2 rows/CTA, 512 threads, high-MLP loops ----------------
__global__ void __launch_bounds__(512) k_attn(
    const int* __restrict__ caps, const float* __restrict__ emb,
    const float* __restrict__ wfull, const float* __restrict__ bfull,
    int t, const f16* __restrict__ h2in)
{
    const int nv = g_nvalid[t];
    const int i0 = blockIdx.x * 2;
    if (i0 >= nv) return;
    const bool two = (i0 + 1 < nv);

    __shared__ float s_a2[2][512];
    __shared__ float s_wf[512];
    __shared__ float s_p[8][128];
    __shared__ float s_sc[2][128];
    __shared__ float s_al[2][128];

    const int tid = threadIdx.x;
    s_a2[0][tid] = g_att2gate[i0*1024 + tid];
    s_a2[1][tid] = two ? g_att2gate[(i0+1)*1024 + tid] : 0.f;
    s_wf[tid] = wfull[tid];
    __syncthreads();

    // scores: j = tid&127, ks = tid>>7 covers 64 k2 each; batched loads MLP=16
    const int j = tid & 127, ks = tid >> 7;
    float p0 = 0.f, p1 = 0.f;
    const __half2* ap = g_att1TP + (size_t)(ks*64)*128 + j;
    for (int kb = 0; kb < 64; kb += 16) {
        float2 vbuf[16];
        #pragma unroll
        for (int u = 0; u < 16; u++)
            vbuf[u] = __half22float2(ap[(size_t)(kb + u)*128]);
        #pragma unroll
        for (int u = 0; u < 16; u++) {
            int k = ks*128 + 2*(kb + u);
            p0 = fmaf(fmaxf(vbuf[u].x + s_a2[0][k],   0.f), s_wf[k],   p0);
            p0 = fmaf(fmaxf(vbuf[u].y + s_a2[0][k+1], 0.f), s_wf[k+1], p0);
            p1 = fmaf(fmaxf(vbuf[u].x + s_a2[1][k],   0.f), s_wf[k],   p1);
            p1 = fmaf(fmaxf(vbuf[u].y + s_a2[1][k+1], 0.f), s_wf[k+1], p1);
        }
    }
    s_p[ks*2][j] = p0;
    s_p[ks*2 + 1][j] = p1;
    __syncthreads();

    if (tid < 256) {
        int row = tid >> 7, jj = tid & 127;
        float sc = s_p[row][jj] + s_p[2+row][jj] + s_p[4+row][jj] + s_p[6+row][jj] + bfull[0];
        s_sc[row][jj] = (jj < nv) ? sc : -3.0e38f;
    }
    __syncthreads();

    if (tid < 64) {
        int row = tid >> 5, l = tid & 31;
        float vv[4], m = -3.0e38f;
        #pragma unroll
        for (int u = 0; u < 4; u++) { vv[u] = s_sc[row][l + 32*u]; m = fmaxf(m, vv[u]); }
        #pragma unroll
        for (int o = 16; o > 0; o >>= 1) m = fmaxf(m, __shfl_xor_sync(0xffffffffu, m, o));
        float sum = 0.f;
        #pragma unroll
        for (int u = 0; u < 4; u++) { vv[u] = expf(vv[u] - m); sum += vv[u]; }
        #pragma unroll
        for (int o = 16; o > 0; o >>= 1) sum += __shfl_xor_sync(0xffffffffu, sum, o);
        float inv = 1.f / sum;
        #pragma unroll
        for (int u = 0; u < 4; u++) s_al[row][l + 32*u] = vv[u] * inv;
    }
    __syncthreads();

    // awe: thread (row = tid>>8, p = tid&255); batched loads MLP=32
    const int row = tid >> 8, p = tid & 255;
    const __half2* ep = g_encH2 + p;
    float ax = 0.f, ay = 0.f;
    for (int jb = 0; jb < 128; jb += 32) {
        float2 ebuf[32];
        #pragma unroll
        for (int u = 0; u < 32; u++)
            ebuf[u] = __half22float2(ep[(size_t)(jb + u)*256]);
        #pragma unroll
        for (int u = 0; u < 32; u++) {
            float a = s_al[row][jb + u];
            ax = fmaf(a, ebuf[u].x, ax);
            ay = fmaf(a, ebuf[u].y, ay);
        }
    }

    const int i = i0 + row;
    if (i < nv) {
        const int d0 = 2*p;
        int cap = caps[g_order[i]*T_ + t];
        f16* xr = g_xcat2 + (size_t)i*1536;
        float2 e2 = *(const float2*)(emb + (size_t)cap*512 + d0);
        xr[d0]   = __float2half(e2.x);
        xr[d0+1] = __float2half(e2.y);
        float2 gt = *(const float2*)(g_att2gate + i*1024 + 512 + d0);
        xr[512 + d0]   = __float2half(gt.x * ax);
        xr[512 + d0+1] = __float2half(gt.y * ay);
        xr[1024 + d0]   = h2in[i*512 + d0];
        xr[1024 + d0+1] = h2in[i*512 + d0 + 1];
    }
}

// ---------------- host launch ----------------
extern "C" void kernel_launch(void* const* d_in, const int* in_sizes, int n_in,
                              void* d_out, int out_size) {
    const float* encoder_out = (const float*)d_in[0];
    const int*   caps        = (const int*)  d_in[1];
    const int*   capl        = (const int*)  d_in[2];
    const float* W_enc  = (const float*)d_in[3];
    const float* b_enc  = (const float*)d_in[4];
    const float* W_dec  = (const float*)d_in[5];
    const float* b_dec  = (const float*)d_in[6];
    const float* W_full = (const float*)d_in[7];
    const float* b_full = (const float*)d_in[8];
    const float* W_init_h = (const float*)d_in[9];
    const float* b_init_h = (const float*)d_in[10];
    const float* W_init_c = (const float*)d_in[11];
    const float* b_init_c = (const float*)d_in[12];
    const float* W_fbeta  = (const float*)d_in[13];
    const float* b_fbeta  = (const float*)d_in[14];
    const float* W_fc     = (const float*)d_in[15];
    const float* b_fc     = (const float*)d_in[16];
    const float* emb      = (const float*)d_in[17];
    const float* W_ih     = (const float*)d_in[18];
    const float* b_ih     = (const float*)d_in[19];
    const float* W_hh     = (const float*)d_in[20];
    const float* b_hh     = (const float*)d_in[21];
    float* out = (float*)d_out;

    float *p_a2g, *p_bc1, *p_bbig;
    f16   *p_h2s, *p_xcat2, *p_Wc1h, *p_Wbigh, *p_Wfch;
    cudaGetSymbolAddress((void**)&p_a2g,   g_att2gate);
    cudaGetSymbolAddress((void**)&p_bc1,   g_bc1);
    cudaGetSymbolAddress((void**)&p_bbig,  g_bbig);
    cudaGetSymbolAddress((void**)&p_h2s,   g_h2s);
    cudaGetSymbolAddress((void**)&p_xcat2, g_xcat2);
    cudaGetSymbolAddress((void**)&p_Wc1h,  g_Wc1h);
    cudaGetSymbolAddress((void**)&p_Wbigh, g_Wbigh);
    cudaGetSymbolAddress((void**)&p_Wfch,  g_Wfch);

    static cudaStream_t s2 = nullptr;
    static cudaEvent_t evF[2], evEnd;
    if (!s2) {
        int lo, hi;
        cudaDeviceGetStreamPriorityRange(&lo, &hi);
        cudaStreamCreateWithPriority(&s2, cudaStreamNonBlocking, lo);
        for (int i = 0; i < 2; i++)
            cudaEventCreateWithFlags(&evF[i], cudaEventDisableTiming);
        cudaEventCreateWithFlags(&evEnd, cudaEventDisableTiming);
        const int SM = 3*STAGE_B;
        cudaFuncSetAttribute(k_mma<1>, cudaFuncAttributeMaxDynamicSharedMemorySize, SM);
        cudaFuncSetAttribute(k_mma<2>, cudaFuncAttributeMaxDynamicSharedMemorySize, SM);
        cudaFuncSetAttribute(k_mma<3>, cudaFuncAttributeMaxDynamicSharedMemorySize, SM);
    }
    const int SMEM_MMA = 3*STAGE_B;

    // ---- prep ----
    k_prep<<<1, 128>>>(capl);
    k_gather<<<128, 128>>>(encoder_out);
    k_buildW<<<7168, 128>>>(W_dec, b_dec, W_fbeta, b_fbeta,
                            W_ih, b_ih, W_hh, b_hh, W_fc);
    k_gemm32t<<<dim3(16,4,3), 256>>>(W_init_h, b_init_h, W_init_c, b_init_c, W_enc, b_enc);
    k_post<<<128, 256>>>();

    // ---- time steps: main chain has ZERO dependencies on preds ----
    for (int t = 0; t < T_; t++) {
        const f16* hin = p_h2s + (size_t)t * HB_;
        f16* hout = p_h2s + (size_t)(t + 1) * HB_;

        k_mma<1><<<dim3(16,4), 256, SMEM_MMA>>>(hin, p_Wc1h, p_bc1, p_a2g, nullptr, 512, t, 1024);
        k_attn<<<64, 512>>>(caps, emb, W_full, b_full, t, hin);
        k_mma<2><<<dim3(32,4), 256, SMEM_MMA>>>(p_xcat2, p_Wbigh, p_bbig, nullptr, hout, 1536, t, 0);
        cudaEventRecord(evF[t & 1], 0);
        cudaStreamWaitEvent(s2, evF[t & 1], 0);
        k_mma<3><<<dim3(64,4), 256, SMEM_MMA, s2>>>(hout, p_Wfch, b_fc, out, nullptr, 512, t, 0);
    }
    cudaEventRecord(evEnd, s2);
    cudaStreamWaitEvent(0, evEnd, 0);
}